// round 1
// baseline (speedup 1.0000x reference)
#include <cuda_runtime.h>
#include <cuda_bf16.h>
#include <cstdint>

// Problem constants
#define NN   50000
#define EE   800000
#define FIN  128
#define FHID 128
#define FOUT 64

// ---------------------------------------------------------------------------
// Scratch (static __device__ arrays — no allocation allowed)
// ---------------------------------------------------------------------------
__device__ float g_h[(size_t)NN * FHID];    // layer-1 GEMM output, then relu'd features
__device__ float g_agg[(size_t)NN * FHID];  // layer-1 aggregation buffer
__device__ float g_h2[(size_t)NN * FOUT];   // layer-2 GEMM output
__device__ float g_deg[NN];                 // degree (float, counted by atomics)
__device__ float g_dis[NN];                 // deg^-1/2

// ---------------------------------------------------------------------------
// Vectorized reduction (no-return atomic add), sm_90+
// ---------------------------------------------------------------------------
__device__ __forceinline__ void red_add_f32x4(float* addr, float4 v) {
    asm volatile("red.global.add.v4.f32 [%0], {%1, %2, %3, %4};"
                 :: "l"(addr), "f"(v.x), "f"(v.y), "f"(v.z), "f"(v.w)
                 : "memory");
}

// ---------------------------------------------------------------------------
// Utility: zero a float buffer (float4 grid-stride)
// ---------------------------------------------------------------------------
__global__ void zero_kernel(float4* __restrict__ p, int n4) {
    int i = blockIdx.x * blockDim.x + threadIdx.x;
    if (i < n4) p[i] = make_float4(0.f, 0.f, 0.f, 0.f);
}

// ---------------------------------------------------------------------------
// Degree counting + dis = rsqrt(deg + 1)   (+1 = self loop)
// ---------------------------------------------------------------------------
__global__ void count_deg_kernel(const int* __restrict__ col, float* __restrict__ deg, int e) {
    int i = blockIdx.x * blockDim.x + threadIdx.x;
    if (i < e) atomicAdd(&deg[col[i]], 1.0f);
}

__global__ void compute_dis_kernel(const float* __restrict__ deg, float* __restrict__ dis, int n) {
    int i = blockIdx.x * blockDim.x + threadIdx.x;
    if (i < n) dis[i] = rsqrtf(deg[i] + 1.0f);
}

// ---------------------------------------------------------------------------
// SIMT fp32 GEMM:  out[N, F] = x[N, 128] @ W[128, F]
// Block: 256 threads. Register tile 4 rows x 4 cols per thread.
// KTILE = 32 (4 k-tiles of the 128-deep reduction).
// FOUTT=128: 32 colgroups x 8 rowgroups -> 32 rows/block
// FOUTT= 64: 16 colgroups x 16 rowgroups -> 64 rows/block
// ---------------------------------------------------------------------------
template <int FOUTT>
__global__ void __launch_bounds__(256)
gemm_kernel(const float* __restrict__ x, const float* __restrict__ W,
            float* __restrict__ out, int nrows) {
    constexpr int KT   = 32;
    constexpr int CG   = FOUTT / 4;       // colgroups
    constexpr int RG   = 256 / CG;        // rowgroups
    constexpr int ROWS = RG * 4;          // rows per block
    constexpr int XSTR = 36;              // padded x-tile row stride (floats), 16B aligned

    __shared__ float Ws[KT * FOUTT];      // [k][col]
    __shared__ float Xs[ROWS * XSTR];     // [r][k], stride 36

    const int tid  = threadIdx.x;
    const int cg   = tid % CG;            // column group (4 cols)
    const int rg   = tid / CG;            // row group (4 rows)
    const int row0 = blockIdx.x * ROWS;

    float acc[4][4];
#pragma unroll
    for (int r = 0; r < 4; r++)
#pragma unroll
        for (int c = 0; c < 4; c++) acc[r][c] = 0.f;

    for (int kt = 0; kt < FIN; kt += KT) {
        // --- load W tile: KT*FOUTT floats, float4 per thread ---
        {
            constexpr int NV = (KT * FOUTT) / 4;   // float4 count
#pragma unroll
            for (int p = tid; p < NV; p += 256) {
                int k  = (p * 4) / FOUTT;
                int c  = (p * 4) % FOUTT;
                float4 wv = *(const float4*)(W + (size_t)(kt + k) * FOUTT + c);
                *(float4*)(Ws + k * FOUTT + c) = wv;
            }
        }
        // --- load x tile: ROWS*KT floats, float4 per thread ---
        {
            constexpr int NV = (ROWS * KT) / 4;
#pragma unroll
            for (int p = tid; p < NV; p += 256) {
                int r  = (p * 4) / KT;
                int kq = (p * 4) % KT;
                float4 xv;
                int grow = row0 + r;
                if (grow < nrows)
                    xv = *(const float4*)(x + (size_t)grow * FIN + kt + kq);
                else
                    xv = make_float4(0.f, 0.f, 0.f, 0.f);
                *(float4*)(Xs + r * XSTR + kq) = xv;
            }
        }
        __syncthreads();

        const float* xsr = Xs + (rg * 4) * XSTR;
#pragma unroll
        for (int k = 0; k < KT; k++) {
            float4 wv = *(const float4*)(Ws + k * FOUTT + cg * 4);
            float x0 = xsr[0 * XSTR + k];
            float x1 = xsr[1 * XSTR + k];
            float x2 = xsr[2 * XSTR + k];
            float x3 = xsr[3 * XSTR + k];
            acc[0][0] += x0 * wv.x; acc[0][1] += x0 * wv.y; acc[0][2] += x0 * wv.z; acc[0][3] += x0 * wv.w;
            acc[1][0] += x1 * wv.x; acc[1][1] += x1 * wv.y; acc[1][2] += x1 * wv.z; acc[1][3] += x1 * wv.w;
            acc[2][0] += x2 * wv.x; acc[2][1] += x2 * wv.y; acc[2][2] += x2 * wv.z; acc[2][3] += x2 * wv.w;
            acc[3][0] += x3 * wv.x; acc[3][1] += x3 * wv.y; acc[3][2] += x3 * wv.z; acc[3][3] += x3 * wv.w;
        }
        __syncthreads();
    }

#pragma unroll
    for (int r = 0; r < 4; r++) {
        int grow = row0 + rg * 4 + r;
        if (grow < nrows) {
            float4 v = make_float4(acc[r][0], acc[r][1], acc[r][2], acc[r][3]);
            *(float4*)(out + (size_t)grow * FOUTT + cg * 4) = v;
        }
    }
}

// ---------------------------------------------------------------------------
// Edge scatter:  agg[col] += h[row] * dis[row] * dis[col]
// F=128: 32 lanes (float4 each) per edge -> 1 edge / warp
// F= 64: 16 lanes per edge             -> 2 edges / warp
// ---------------------------------------------------------------------------
template <int F>
__global__ void __launch_bounds__(256)
scatter_kernel(const float* __restrict__ h,
               const int* __restrict__ row, const int* __restrict__ col,
               const float* __restrict__ dis,
               float* __restrict__ agg, int e) {
    constexpr int LPE = F / 4;          // lanes per edge
    const int gtid = blockIdx.x * blockDim.x + threadIdx.x;
    const int lane = gtid & 31;
    const int warp = gtid >> 5;
    const int edge = warp * (32 / LPE) + lane / LPE;
    const int sub  = lane % LPE;
    if (edge >= e) return;

    const int r = __ldg(row + edge);
    const int c = __ldg(col + edge);
    const float norm = __ldg(dis + r) * __ldg(dis + c);

    float4 v = *(const float4*)(h + (size_t)r * F + sub * 4);
    v.x *= norm; v.y *= norm; v.z *= norm; v.w *= norm;
    red_add_f32x4(agg + (size_t)c * F + sub * 4, v);
}

// ---------------------------------------------------------------------------
// Finalize layer 1:  h = relu(agg + h * dis^2 + b)     (in place into g_h)
// one thread per float4 group
// ---------------------------------------------------------------------------
__global__ void finalize1_kernel(float* __restrict__ h, const float* __restrict__ agg,
                                 const float* __restrict__ dis, const float* __restrict__ b,
                                 int n) {
    int idx = blockIdx.x * blockDim.x + threadIdx.x;   // over n * (FHID/4)
    constexpr int G = FHID / 4;
    if (idx >= n * G) return;
    int i  = idx / G;
    int f4 = idx % G;
    float d2 = dis[i]; d2 *= d2;
    float4 a  = *(const float4*)(agg + (size_t)idx * 4);
    float4 hv = *(const float4*)(h + (size_t)idx * 4);
    float4 bv = *(const float4*)(b + f4 * 4);
    float4 o;
    o.x = fmaxf(a.x + hv.x * d2 + bv.x, 0.f);
    o.y = fmaxf(a.y + hv.y * d2 + bv.y, 0.f);
    o.z = fmaxf(a.z + hv.z * d2 + bv.z, 0.f);
    o.w = fmaxf(a.w + hv.w * d2 + bv.w, 0.f);
    *(float4*)(h + (size_t)idx * 4) = o;
}

// ---------------------------------------------------------------------------
// Finalize layer 2:  out += h2 * dis^2 + b2   (out already holds scatter sum)
// ---------------------------------------------------------------------------
__global__ void finalize2_kernel(float* __restrict__ out, const float* __restrict__ h2,
                                 const float* __restrict__ dis, const float* __restrict__ b,
                                 int n) {
    int idx = blockIdx.x * blockDim.x + threadIdx.x;   // over n * (FOUT/4)
    constexpr int G = FOUT / 4;
    if (idx >= n * G) return;
    int i  = idx / G;
    int f4 = idx % G;
    float d2 = dis[i]; d2 *= d2;
    float4 o  = *(const float4*)(out + (size_t)idx * 4);
    float4 hv = *(const float4*)(h2 + (size_t)idx * 4);
    float4 bv = *(const float4*)(b + f4 * 4);
    o.x += hv.x * d2 + bv.x;
    o.y += hv.y * d2 + bv.y;
    o.z += hv.z * d2 + bv.z;
    o.w += hv.w * d2 + bv.w;
    *(float4*)(out + (size_t)idx * 4) = o;
}

// ---------------------------------------------------------------------------
// Launch
// ---------------------------------------------------------------------------
extern "C" void kernel_launch(void* const* d_in, const int* in_sizes, int n_in,
                              void* d_out, int out_size) {
    const float* x  = (const float*)d_in[0];
    const int*   ei = (const int*)d_in[1];     // [2, E]: row = ei, col = ei + E
    const float* W1 = (const float*)d_in[2];
    const float* b1 = (const float*)d_in[3];
    const float* W2 = (const float*)d_in[4];
    const float* b2 = (const float*)d_in[5];
    float* out = (float*)d_out;

    const int* row = ei;
    const int* col = ei + EE;

    // device symbol addresses (static arrays: take address directly via a kernel arg)
    // We can take addresses of __device__ arrays from host only via cudaGetSymbolAddress,
    // but passing the symbol directly in a kernel argument is invalid host-side.
    // Instead, obtain them once per launch (cheap, capture-safe, no allocation).
    static float *p_h = nullptr, *p_agg = nullptr, *p_h2 = nullptr, *p_deg = nullptr, *p_dis = nullptr;
    if (!p_h) {
        cudaGetSymbolAddress((void**)&p_h,   g_h);
        cudaGetSymbolAddress((void**)&p_agg, g_agg);
        cudaGetSymbolAddress((void**)&p_h2,  g_h2);
        cudaGetSymbolAddress((void**)&p_deg, g_deg);
        cudaGetSymbolAddress((void**)&p_dis, g_dis);
    }

    // ---- degree + dis ----
    {
        int n4 = NN / 4;  // 50000 % 4 == 0
        zero_kernel<<<(n4 + 255) / 256, 256>>>((float4*)p_deg, n4);
        count_deg_kernel<<<(EE + 255) / 256, 256>>>(col, p_deg, EE);
        compute_dis_kernel<<<(NN + 255) / 256, 256>>>(p_deg, p_dis, NN);
    }

    // ---- layer 1: GEMM ----
    {
        int blocks = (NN + 31) / 32;   // 32 rows/block for FOUTT=128
        gemm_kernel<128><<<blocks, 256>>>(x, W1, p_h, NN);
    }
    // ---- zero agg ----
    {
        int n4 = (NN * FHID) / 4;
        zero_kernel<<<(n4 + 255) / 256, 256>>>((float4*)p_agg, n4);
    }
    // ---- scatter 1 ----
    {
        long long threads = (long long)EE * 32;   // 1 edge per warp
        int blocks = (int)((threads + 255) / 256);
        scatter_kernel<128><<<blocks, 256>>>(p_h, row, col, p_dis, p_agg, EE);
    }
    // ---- finalize 1 (relu) ----
    {
        int n = NN * (FHID / 4);
        finalize1_kernel<<<(n + 255) / 256, 256>>>(p_h, p_agg, p_dis, b1, NN);
    }
    // ---- layer 2: GEMM ----
    {
        int blocks = (NN + 63) / 64;   // 64 rows/block for FOUTT=64
        gemm_kernel<64><<<blocks, 256>>>(p_h, W2, p_h2, NN);
    }
    // ---- zero d_out ----
    {
        int n4 = (NN * FOUT) / 4;
        zero_kernel<<<(n4 + 255) / 256, 256>>>((float4*)out, n4);
    }
    // ---- scatter 2 ----
    {
        long long threads = (long long)EE * 16;   // 2 edges per warp
        int blocks = (int)((threads + 255) / 256);
        scatter_kernel<64><<<blocks, 256>>>(p_h2, row, col, p_dis, out, EE);
    }
    // ---- finalize 2 ----
    {
        int n = NN * (FOUT / 4);
        finalize2_kernel<<<(n + 255) / 256, 256>>>(out, p_h2, p_dis, b2, NN);
    }
}

// round 2
// speedup vs baseline: 1.0115x; 1.0115x over previous
#include <cuda_runtime.h>
#include <cuda_bf16.h>
#include <cstdint>

// Problem constants
#define NN   50000
#define EE   800000
#define FIN  128
#define FHID 128
#define FOUT 64

// ---------------------------------------------------------------------------
// Scratch (static __device__ arrays — no allocation allowed)
// ---------------------------------------------------------------------------
__device__ float g_h[(size_t)NN * FHID];    // layer-1: holds hs = (x@W1)*dis, then relu'd features
__device__ float g_agg[(size_t)NN * FHID];  // layer-1 aggregation buffer
__device__ float g_h2[(size_t)NN * FOUT];   // layer-2: holds hs2 = (h@W2)*dis
__device__ float g_deg[NN];                 // degree (float, counted by atomics)
__device__ float g_dis[NN];                 // deg^-1/2

// ---------------------------------------------------------------------------
// Vectorized reduction (no-return atomic add), sm_90+
// ---------------------------------------------------------------------------
__device__ __forceinline__ void red_add_f32x4(float* addr, float4 v) {
    asm volatile("red.global.add.v4.f32 [%0], {%1, %2, %3, %4};"
                 :: "l"(addr), "f"(v.x), "f"(v.y), "f"(v.z), "f"(v.w)
                 : "memory");
}

// ---------------------------------------------------------------------------
// Utility: zero a float buffer (float4)
// ---------------------------------------------------------------------------
__global__ void zero_kernel(float4* __restrict__ p, int n4) {
    int i = blockIdx.x * blockDim.x + threadIdx.x;
    if (i < n4) p[i] = make_float4(0.f, 0.f, 0.f, 0.f);
}

// ---------------------------------------------------------------------------
// Degree counting + dis = rsqrt(deg + 1)   (+1 = self loop)
// ---------------------------------------------------------------------------
__global__ void count_deg_kernel(const int* __restrict__ col, float* __restrict__ deg, int e) {
    int i = blockIdx.x * blockDim.x + threadIdx.x;
    if (i < e) atomicAdd(&deg[col[i]], 1.0f);
}

__global__ void compute_dis_kernel(const float* __restrict__ deg, float* __restrict__ dis, int n) {
    int i = blockIdx.x * blockDim.x + threadIdx.x;
    if (i < n) dis[i] = rsqrtf(deg[i] + 1.0f);
}

// ---------------------------------------------------------------------------
// SIMT fp32 GEMM:  out[N, F] = x[N, 128] @ W[128, F]   (optionally * dis[row])
//
// Block: 256 threads. Register tile 4 rows x 4 cols per thread. KT = 32.
// Xs is stored TRANSPOSED ([k][row]) with a rotation swizzle
//     col(r, k) = (r + (k & ~3)) & (ROWS-1)
// so that:
//   - the transposed scalar stores are bank-conflict-free
//     (bank = (r + kq) mod 32 spans all 32 banks across a warp)
//   - the compute read is a single aligned float4 at a warp-uniform address
//     (broadcast -> 1 wavefront instead of 4 scalar LDS)
// This flips the kernel from L1-wavefront-bound (77.6%) to FMA-bound.
// ---------------------------------------------------------------------------
template <int FOUTT, bool SCALE>
__global__ void __launch_bounds__(256)
gemm_kernel(const float* __restrict__ x, const float* __restrict__ W,
            float* __restrict__ out, const float* __restrict__ dis, int nrows) {
    constexpr int KT    = 32;
    constexpr int CG    = FOUTT / 4;       // colgroups (32 or 16)
    constexpr int RG    = 256 / CG;        // rowgroups (8 or 16)
    constexpr int ROWS  = RG * 4;          // rows per block (32 or 64)
    constexpr int RMASK = ROWS - 1;

    __shared__ float Ws[KT * FOUTT];       // [k][col]
    __shared__ float Xs[KT * ROWS];        // [k][swizzled row]

    const int tid  = threadIdx.x;
    const int cg   = tid % CG;
    const int rg   = tid / CG;
    const int row0 = blockIdx.x * ROWS;

    float acc[4][4];
#pragma unroll
    for (int r = 0; r < 4; r++)
#pragma unroll
        for (int c = 0; c < 4; c++) acc[r][c] = 0.f;

    for (int kt = 0; kt < FIN; kt += KT) {
        // --- load W tile: KT*FOUTT floats, float4 per thread ---
        {
            constexpr int NV = (KT * FOUTT) / 4;
#pragma unroll
            for (int p = tid; p < NV; p += 256) {
                int k = (p * 4) / FOUTT;
                int c = (p * 4) % FOUTT;
                *(float4*)(Ws + k * FOUTT + c) =
                    *(const float4*)(W + (size_t)(kt + k) * FOUTT + c);
            }
        }
        // --- load x tile, transposed + rotated store ---
        {
            constexpr int NV = (ROWS * KT) / 4;
#pragma unroll
            for (int p = tid; p < NV; p += 256) {
                int r  = (p * 4) / KT;
                int kq = (p * 4) % KT;          // multiple of 4
                float4 xv;
                int grow = row0 + r;
                if (grow < nrows)
                    xv = *(const float4*)(x + (size_t)grow * FIN + kt + kq);
                else
                    xv = make_float4(0.f, 0.f, 0.f, 0.f);
                int c = (r + kq) & RMASK;       // rotation swizzle
                Xs[(kq + 0) * ROWS + c] = xv.x;
                Xs[(kq + 1) * ROWS + c] = xv.y;
                Xs[(kq + 2) * ROWS + c] = xv.z;
                Xs[(kq + 3) * ROWS + c] = xv.w;
            }
        }
        __syncthreads();

#pragma unroll
        for (int k = 0; k < KT; k++) {
            float4 wv = *(const float4*)(Ws + k * FOUTT + cg * 4);
            float4 xv = *(const float4*)(Xs + k * ROWS + ((rg * 4 + (k & ~3)) & RMASK));
            acc[0][0] += xv.x * wv.x; acc[0][1] += xv.x * wv.y; acc[0][2] += xv.x * wv.z; acc[0][3] += xv.x * wv.w;
            acc[1][0] += xv.y * wv.x; acc[1][1] += xv.y * wv.y; acc[1][2] += xv.y * wv.z; acc[1][3] += xv.y * wv.w;
            acc[2][0] += xv.z * wv.x; acc[2][1] += xv.z * wv.y; acc[2][2] += xv.z * wv.z; acc[2][3] += xv.z * wv.w;
            acc[3][0] += xv.w * wv.x; acc[3][1] += xv.w * wv.y; acc[3][2] += xv.w * wv.z; acc[3][3] += xv.w * wv.w;
        }
        __syncthreads();
    }

#pragma unroll
    for (int r = 0; r < 4; r++) {
        int grow = row0 + rg * 4 + r;
        if (grow < nrows) {
            float s = SCALE ? __ldg(dis + grow) : 1.0f;
            float4 v = make_float4(acc[r][0] * s, acc[r][1] * s,
                                   acc[r][2] * s, acc[r][3] * s);
            *(float4*)(out + (size_t)grow * FOUTT + cg * 4) = v;
        }
    }
}

// ---------------------------------------------------------------------------
// Edge scatter:  agg[col] += hs[row] * dis[col]      (hs already = h*dis[row])
// F=128: 32 lanes (float4 each) per edge -> 1 edge / warp
// F= 64: 16 lanes per edge             -> 2 edges / warp
// ---------------------------------------------------------------------------
template <int F>
__global__ void __launch_bounds__(256)
scatter_kernel(const float* __restrict__ hs,
               const int* __restrict__ row, const int* __restrict__ col,
               const float* __restrict__ dis,
               float* __restrict__ agg, int e) {
    constexpr int LPE = F / 4;          // lanes per edge
    const int gtid = blockIdx.x * blockDim.x + threadIdx.x;
    const int lane = gtid & 31;
    const int warp = gtid >> 5;
    const int edge = warp * (32 / LPE) + lane / LPE;
    const int sub  = lane % LPE;
    if (edge >= e) return;

    const int r = __ldg(row + edge);
    const int c = __ldg(col + edge);
    const float norm = __ldg(dis + c);

    float4 v = *(const float4*)(hs + (size_t)r * F + sub * 4);
    v.x *= norm; v.y *= norm; v.z *= norm; v.w *= norm;
    red_add_f32x4(agg + (size_t)c * F + sub * 4, v);
}

// ---------------------------------------------------------------------------
// Finalize layer 1:  h = relu(agg + hs * dis + b)    (hs = h*dis already)
// ---------------------------------------------------------------------------
__global__ void finalize1_kernel(float* __restrict__ h, const float* __restrict__ agg,
                                 const float* __restrict__ dis, const float* __restrict__ b,
                                 int n) {
    int idx = blockIdx.x * blockDim.x + threadIdx.x;   // over n * (FHID/4)
    constexpr int G = FHID / 4;
    if (idx >= n * G) return;
    int i  = idx / G;
    int f4 = idx % G;
    float d = dis[i];
    float4 a  = *(const float4*)(agg + (size_t)idx * 4);
    float4 hv = *(const float4*)(h + (size_t)idx * 4);
    float4 bv = *(const float4*)(b + f4 * 4);
    float4 o;
    o.x = fmaxf(a.x + hv.x * d + bv.x, 0.f);
    o.y = fmaxf(a.y + hv.y * d + bv.y, 0.f);
    o.z = fmaxf(a.z + hv.z * d + bv.z, 0.f);
    o.w = fmaxf(a.w + hv.w * d + bv.w, 0.f);
    *(float4*)(h + (size_t)idx * 4) = o;
}

// ---------------------------------------------------------------------------
// Finalize layer 2:  out += hs2 * dis + b2   (out already holds scatter sum)
// ---------------------------------------------------------------------------
__global__ void finalize2_kernel(float* __restrict__ out, const float* __restrict__ hs2,
                                 const float* __restrict__ dis, const float* __restrict__ b,
                                 int n) {
    int idx = blockIdx.x * blockDim.x + threadIdx.x;   // over n * (FOUT/4)
    constexpr int G = FOUT / 4;
    if (idx >= n * G) return;
    int i  = idx / G;
    int f4 = idx % G;
    float d = dis[i];
    float4 o  = *(const float4*)(out + (size_t)idx * 4);
    float4 hv = *(const float4*)(hs2 + (size_t)idx * 4);
    float4 bv = *(const float4*)(b + f4 * 4);
    o.x += hv.x * d + bv.x;
    o.y += hv.y * d + bv.y;
    o.z += hv.z * d + bv.z;
    o.w += hv.w * d + bv.w;
    *(float4*)(out + (size_t)idx * 4) = o;
}

// ---------------------------------------------------------------------------
// Launch
// ---------------------------------------------------------------------------
extern "C" void kernel_launch(void* const* d_in, const int* in_sizes, int n_in,
                              void* d_out, int out_size) {
    const float* x  = (const float*)d_in[0];
    const int*   ei = (const int*)d_in[1];     // [2, E]: row = ei, col = ei + E
    const float* W1 = (const float*)d_in[2];
    const float* b1 = (const float*)d_in[3];
    const float* W2 = (const float*)d_in[4];
    const float* b2 = (const float*)d_in[5];
    float* out = (float*)d_out;

    const int* row = ei;
    const int* col = ei + EE;

    static float *p_h = nullptr, *p_agg = nullptr, *p_h2 = nullptr, *p_deg = nullptr, *p_dis = nullptr;
    if (!p_h) {
        cudaGetSymbolAddress((void**)&p_h,   g_h);
        cudaGetSymbolAddress((void**)&p_agg, g_agg);
        cudaGetSymbolAddress((void**)&p_h2,  g_h2);
        cudaGetSymbolAddress((void**)&p_deg, g_deg);
        cudaGetSymbolAddress((void**)&p_dis, g_dis);
    }

    // ---- degree + dis ----
    {
        int n4 = NN / 4;  // 50000 % 4 == 0
        zero_kernel<<<(n4 + 255) / 256, 256>>>((float4*)p_deg, n4);
        count_deg_kernel<<<(EE + 255) / 256, 256>>>(col, p_deg, EE);
        compute_dis_kernel<<<(NN + 255) / 256, 256>>>(p_deg, p_dis, NN);
    }

    // ---- layer 1: GEMM (writes hs = (x@W1)*dis) ----
    {
        int blocks = (NN + 31) / 32;   // 32 rows/block for FOUTT=128
        gemm_kernel<128, true><<<blocks, 256>>>(x, W1, p_h, p_dis, NN);
    }
    // ---- zero agg ----
    {
        int n4 = (NN * FHID) / 4;
        zero_kernel<<<(n4 + 255) / 256, 256>>>((float4*)p_agg, n4);
    }
    // ---- scatter 1 ----
    {
        long long threads = (long long)EE * 32;   // 1 edge per warp
        int blocks = (int)((threads + 255) / 256);
        scatter_kernel<128><<<blocks, 256>>>(p_h, row, col, p_dis, p_agg, EE);
    }
    // ---- finalize 1 (relu) ----
    {
        int n = NN * (FHID / 4);
        finalize1_kernel<<<(n + 255) / 256, 256>>>(p_h, p_agg, p_dis, b1, NN);
    }
    // ---- layer 2: GEMM (writes hs2 = (h@W2)*dis) ----
    {
        int blocks = (NN + 63) / 64;   // 64 rows/block for FOUTT=64
        gemm_kernel<64, true><<<blocks, 256>>>(p_h, W2, p_h2, p_dis, NN);
    }
    // ---- zero d_out ----
    {
        int n4 = (NN * FOUT) / 4;
        zero_kernel<<<(n4 + 255) / 256, 256>>>((float4*)out, n4);
    }
    // ---- scatter 2 ----
    {
        long long threads = (long long)EE * 16;   // 2 edges per warp
        int blocks = (int)((threads + 255) / 256);
        scatter_kernel<64><<<blocks, 256>>>(p_h2, row, col, p_dis, out, EE);
    }
    // ---- finalize 2 ----
    {
        int n = NN * (FOUT / 4);
        finalize2_kernel<<<(n + 255) / 256, 256>>>(out, p_h2, p_dis, b2, NN);
    }
}

// round 3
// speedup vs baseline: 1.6138x; 1.5954x over previous
#include <cuda_runtime.h>
#include <cuda_bf16.h>
#include <cstdint>

// Problem constants
#define NN   50000
#define EE   800000
#define FIN  128
#define FHID 128
#define FOUT 64

// ---------------------------------------------------------------------------
// Scratch (static __device__ arrays — no allocation allowed)
// ---------------------------------------------------------------------------
__device__ float g_h[(size_t)NN * FHID];    // hs1 = (x@W1)*dis
__device__ float g_agg[(size_t)NN * FHID];  // h   = relu(dis*(sum+self)+b1)
__device__ float g_h2[(size_t)NN * FOUT];   // hs2 = (h@W2)*dis
__device__ int   g_deg[NN];                 // in-degree histogram
__device__ float g_dis[NN];                 // (deg+1)^-1/2
__device__ int   g_starts[NN + 1];          // CSR row starts
__device__ int   g_cursor[NN];              // atomic fill cursors
__device__ int   g_csr_row[EE];             // source node per CSR slot
__device__ int   g_blockoff[64];            // scan block offsets

// ---------------------------------------------------------------------------
// Zero int buffer
// ---------------------------------------------------------------------------
__global__ void zero_int_kernel(int* __restrict__ p, int n) {
    int i = blockIdx.x * blockDim.x + threadIdx.x;
    if (i < n) p[i] = 0;
}

// ---------------------------------------------------------------------------
// Degree histogram + dis = rsqrt(deg + 1)
// ---------------------------------------------------------------------------
__global__ void count_deg_kernel(const int* __restrict__ col, int* __restrict__ deg, int e) {
    int i = blockIdx.x * blockDim.x + threadIdx.x;
    if (i < e) atomicAdd(&deg[col[i]], 1);
}

__global__ void compute_dis_kernel(const int* __restrict__ deg, float* __restrict__ dis, int n) {
    int i = blockIdx.x * blockDim.x + threadIdx.x;
    if (i < n) dis[i] = rsqrtf((float)deg[i] + 1.0f);
}

// ---------------------------------------------------------------------------
// Prefix scan of degree histogram -> CSR starts (3 phases)
// Phase 1: per-block (1024 elems) totals
// ---------------------------------------------------------------------------
__global__ void __launch_bounds__(256)
scan1_kernel(const int* __restrict__ deg, int* __restrict__ blocksum, int n) {
    __shared__ int wsum[8];
    int t = threadIdx.x, b = blockIdx.x;
    int base = b * 1024 + t * 4;
    int s = 0;
#pragma unroll
    for (int j = 0; j < 4; j++) {
        int idx = base + j;
        s += (idx < n) ? deg[idx] : 0;
    }
    // warp reduce
#pragma unroll
    for (int o = 16; o > 0; o >>= 1) s += __shfl_down_sync(0xffffffffu, s, o);
    if ((t & 31) == 0) wsum[t >> 5] = s;
    __syncthreads();
    if (t == 0) {
        int tot = 0;
#pragma unroll
        for (int w = 0; w < 8; w++) tot += wsum[w];
        blocksum[b] = tot;
    }
}

// Phase 2: serial exclusive scan of block sums (tiny), writes starts[NN]
__global__ void scan2_kernel(const int* __restrict__ blocksum, int* __restrict__ blockoff,
                             int* __restrict__ starts, int nblk, int n) {
    if (threadIdx.x == 0 && blockIdx.x == 0) {
        int run = 0;
        for (int i = 0; i < nblk; i++) { blockoff[i] = run; run += blocksum[i]; }
        starts[n] = run;
    }
}

// Phase 3: per-block exclusive scan with global offset -> starts + cursor
__global__ void __launch_bounds__(256)
scan3_kernel(const int* __restrict__ deg, const int* __restrict__ blockoff,
             int* __restrict__ starts, int* __restrict__ cursor, int n) {
    __shared__ int wtot[8];
    int t = threadIdx.x, b = blockIdx.x;
    int lane = t & 31, wid = t >> 5;
    int base = b * 1024 + t * 4;
    int v[4];
#pragma unroll
    for (int j = 0; j < 4; j++) {
        int idx = base + j;
        v[j] = (idx < n) ? deg[idx] : 0;
    }
    int tsum = v[0] + v[1] + v[2] + v[3];
    // warp inclusive scan
    int incl = tsum;
#pragma unroll
    for (int o = 1; o < 32; o <<= 1) {
        int u = __shfl_up_sync(0xffffffffu, incl, o);
        if (lane >= o) incl += u;
    }
    if (lane == 31) wtot[wid] = incl;
    __syncthreads();
    int woff = 0;
#pragma unroll
    for (int w = 0; w < 8; w++) woff += (w < wid) ? wtot[w] : 0;
    int excl = blockoff[b] + woff + incl - tsum;
#pragma unroll
    for (int j = 0; j < 4; j++) {
        int idx = base + j;
        if (idx < n) { starts[idx] = excl; cursor[idx] = excl; }
        excl += v[j];
    }
}

// ---------------------------------------------------------------------------
// CSR fill: slot = cursor[col]++; csr_row[slot] = row
// ---------------------------------------------------------------------------
__global__ void fill_kernel(const int* __restrict__ row, const int* __restrict__ col,
                            int* __restrict__ cursor, int* __restrict__ csr_row, int e) {
    int i = blockIdx.x * blockDim.x + threadIdx.x;
    if (i < e) {
        int slot = atomicAdd(&cursor[col[i]], 1);
        csr_row[slot] = row[i];
    }
}

// ---------------------------------------------------------------------------
// SIMT fp32 GEMM:  out[N, F] = (x[N, 128] @ W[128, F]) * dis[row]
// (unchanged from round 2 — near the fp32 SIMT issue floor)
// ---------------------------------------------------------------------------
template <int FOUTT>
__global__ void __launch_bounds__(256)
gemm_kernel(const float* __restrict__ x, const float* __restrict__ W,
            float* __restrict__ out, const float* __restrict__ dis, int nrows) {
    constexpr int KT    = 32;
    constexpr int CG    = FOUTT / 4;
    constexpr int RG    = 256 / CG;
    constexpr int ROWS  = RG * 4;
    constexpr int RMASK = ROWS - 1;

    __shared__ float Ws[KT * FOUTT];
    __shared__ float Xs[KT * ROWS];

    const int tid  = threadIdx.x;
    const int cg   = tid % CG;
    const int rg   = tid / CG;
    const int row0 = blockIdx.x * ROWS;

    float acc[4][4];
#pragma unroll
    for (int r = 0; r < 4; r++)
#pragma unroll
        for (int c = 0; c < 4; c++) acc[r][c] = 0.f;

    for (int kt = 0; kt < FIN; kt += KT) {
        {
            constexpr int NV = (KT * FOUTT) / 4;
#pragma unroll
            for (int p = tid; p < NV; p += 256) {
                int k = (p * 4) / FOUTT;
                int c = (p * 4) % FOUTT;
                *(float4*)(Ws + k * FOUTT + c) =
                    *(const float4*)(W + (size_t)(kt + k) * FOUTT + c);
            }
        }
        {
            constexpr int NV = (ROWS * KT) / 4;
#pragma unroll
            for (int p = tid; p < NV; p += 256) {
                int r  = (p * 4) / KT;
                int kq = (p * 4) % KT;
                float4 xv;
                int grow = row0 + r;
                if (grow < nrows)
                    xv = *(const float4*)(x + (size_t)grow * FIN + kt + kq);
                else
                    xv = make_float4(0.f, 0.f, 0.f, 0.f);
                int c = (r + kq) & RMASK;
                Xs[(kq + 0) * ROWS + c] = xv.x;
                Xs[(kq + 1) * ROWS + c] = xv.y;
                Xs[(kq + 2) * ROWS + c] = xv.z;
                Xs[(kq + 3) * ROWS + c] = xv.w;
            }
        }
        __syncthreads();

#pragma unroll
        for (int k = 0; k < KT; k++) {
            float4 wv = *(const float4*)(Ws + k * FOUTT + cg * 4);
            float4 xv = *(const float4*)(Xs + k * ROWS + ((rg * 4 + (k & ~3)) & RMASK));
            acc[0][0] += xv.x * wv.x; acc[0][1] += xv.x * wv.y; acc[0][2] += xv.x * wv.z; acc[0][3] += xv.x * wv.w;
            acc[1][0] += xv.y * wv.x; acc[1][1] += xv.y * wv.y; acc[1][2] += xv.y * wv.z; acc[1][3] += xv.y * wv.w;
            acc[2][0] += xv.z * wv.x; acc[2][1] += xv.z * wv.y; acc[2][2] += xv.z * wv.z; acc[2][3] += xv.z * wv.w;
            acc[3][0] += xv.w * wv.x; acc[3][1] += xv.w * wv.y; acc[3][2] += xv.w * wv.z; acc[3][3] += xv.w * wv.w;
        }
        __syncthreads();
    }

#pragma unroll
    for (int r = 0; r < 4; r++) {
        int grow = row0 + rg * 4 + r;
        if (grow < nrows) {
            float s = __ldg(dis + grow);
            float4 v = make_float4(acc[r][0] * s, acc[r][1] * s,
                                   acc[r][2] * s, acc[r][3] * s);
            *(float4*)(out + (size_t)grow * FOUTT + cg * 4) = v;
        }
    }
}

// ---------------------------------------------------------------------------
// CSR segment-sum aggregate (fused self-loop + dis scale + bias [+ relu]):
//   out[c] = act( dis[c] * ( hs[c] + sum_{e in csr[c]} hs[row_e] ) + bias )
// F=128: 32 lanes (float4 each) per node; F=64: 16 lanes per node.
// Two accumulators to expose load-level parallelism.
// ---------------------------------------------------------------------------
template <int F, bool RELU>
__global__ void __launch_bounds__(256)
aggregate_kernel(const float* __restrict__ hs,
                 const int* __restrict__ csr_row, const int* __restrict__ starts,
                 const float* __restrict__ dis, const float* __restrict__ bias,
                 float* __restrict__ out, int n) {
    constexpr int LPN = F / 4;                 // lanes per node
    const int gtid = blockIdx.x * blockDim.x + threadIdx.x;
    const int node = gtid / LPN;
    const int sub  = gtid % LPN;
    if (node >= n) return;

    const int beg = __ldg(starts + node);
    const int end = __ldg(starts + node + 1);

    // self loop
    float4 a0 = *(const float4*)(hs + (size_t)node * F + sub * 4);
    float4 a1 = make_float4(0.f, 0.f, 0.f, 0.f);

    int e = beg;
    for (; e + 1 < end; e += 2) {
        int r0 = __ldg(csr_row + e);
        int r1 = __ldg(csr_row + e + 1);
        float4 v0 = *(const float4*)(hs + (size_t)r0 * F + sub * 4);
        float4 v1 = *(const float4*)(hs + (size_t)r1 * F + sub * 4);
        a0.x += v0.x; a0.y += v0.y; a0.z += v0.z; a0.w += v0.w;
        a1.x += v1.x; a1.y += v1.y; a1.z += v1.z; a1.w += v1.w;
    }
    if (e < end) {
        int r0 = __ldg(csr_row + e);
        float4 v0 = *(const float4*)(hs + (size_t)r0 * F + sub * 4);
        a0.x += v0.x; a0.y += v0.y; a0.z += v0.z; a0.w += v0.w;
    }

    const float d = __ldg(dis + node);
    float4 bv = *(const float4*)(bias + sub * 4);
    float4 o;
    o.x = (a0.x + a1.x) * d + bv.x;
    o.y = (a0.y + a1.y) * d + bv.y;
    o.z = (a0.z + a1.z) * d + bv.z;
    o.w = (a0.w + a1.w) * d + bv.w;
    if (RELU) {
        o.x = fmaxf(o.x, 0.f); o.y = fmaxf(o.y, 0.f);
        o.z = fmaxf(o.z, 0.f); o.w = fmaxf(o.w, 0.f);
    }
    *(float4*)(out + (size_t)node * F + sub * 4) = o;
}

// ---------------------------------------------------------------------------
// Launch
// ---------------------------------------------------------------------------
extern "C" void kernel_launch(void* const* d_in, const int* in_sizes, int n_in,
                              void* d_out, int out_size) {
    const float* x  = (const float*)d_in[0];
    const int*   ei = (const int*)d_in[1];     // [2, E]: row = ei, col = ei + E
    const float* W1 = (const float*)d_in[2];
    const float* b1 = (const float*)d_in[3];
    const float* W2 = (const float*)d_in[4];
    const float* b2 = (const float*)d_in[5];
    float* out = (float*)d_out;

    const int* row = ei;
    const int* col = ei + EE;

    static float *p_h = nullptr, *p_agg = nullptr, *p_h2 = nullptr, *p_dis = nullptr;
    static int *p_deg = nullptr, *p_starts = nullptr, *p_cursor = nullptr,
               *p_csr = nullptr, *p_boff = nullptr;
    if (!p_h) {
        cudaGetSymbolAddress((void**)&p_h,      g_h);
        cudaGetSymbolAddress((void**)&p_agg,    g_agg);
        cudaGetSymbolAddress((void**)&p_h2,     g_h2);
        cudaGetSymbolAddress((void**)&p_dis,    g_dis);
        cudaGetSymbolAddress((void**)&p_deg,    g_deg);
        cudaGetSymbolAddress((void**)&p_starts, g_starts);
        cudaGetSymbolAddress((void**)&p_cursor, g_cursor);
        cudaGetSymbolAddress((void**)&p_csr,    g_csr_row);
        cudaGetSymbolAddress((void**)&p_boff,   g_blockoff);
    }

    const int NBLK = (NN + 1023) / 1024;   // 49

    // ---- degree histogram + dis ----
    zero_int_kernel<<<(NN + 255) / 256, 256>>>(p_deg, NN);
    count_deg_kernel<<<(EE + 255) / 256, 256>>>(col, p_deg, EE);
    compute_dis_kernel<<<(NN + 255) / 256, 256>>>(p_deg, p_dis, NN);

    // ---- CSR build (runs while nothing depends on it until aggregate) ----
    scan1_kernel<<<NBLK, 256>>>(p_deg, p_boff + 0, NN);          // blocksum in g_blockoff? no:
    // use separate regions of g_blockoff: [0..48] blocksum -> scanned in place
    scan2_kernel<<<1, 32>>>(p_boff, p_boff, p_starts, NBLK, NN); // in-place exclusive ok (serial)
    scan3_kernel<<<NBLK, 256>>>(p_deg, p_boff, p_starts, p_cursor, NN);
    fill_kernel<<<(EE + 255) / 256, 256>>>(row, col, p_cursor, p_csr, EE);

    // ---- layer 1: GEMM (hs1 = (x@W1)*dis) ----
    gemm_kernel<128><<<(NN + 31) / 32, 256>>>(x, W1, p_h, p_dis, NN);

    // ---- layer 1 aggregate (fused self-loop+scale+bias+relu) -> g_agg = h ----
    {
        long long threads = (long long)NN * 32;
        aggregate_kernel<128, true><<<(int)((threads + 255) / 256), 256>>>(
            p_h, p_csr, p_starts, p_dis, b1, p_agg, NN);
    }

    // ---- layer 2: GEMM (hs2 = (h@W2)*dis) ----
    gemm_kernel<64><<<(NN + 63) / 64, 256>>>(p_agg, W2, p_h2, p_dis, NN);

    // ---- layer 2 aggregate -> d_out ----
    {
        long long threads = (long long)NN * 16;
        aggregate_kernel<64, false><<<(int)((threads + 255) / 256), 256>>>(
            p_h2, p_csr, p_starts, p_dis, b2, out, NN);
    }
}

// round 4
// speedup vs baseline: 1.9976x; 1.2379x over previous
#include <cuda_runtime.h>
#include <cuda_bf16.h>
#include <cstdint>

// Problem constants
#define NN   50000
#define EE   800000
#define FIN  128
#define FHID 128
#define FOUT 64

// ---------------------------------------------------------------------------
// Scratch (static __device__ arrays — no allocation allowed)
// ---------------------------------------------------------------------------
__device__ float g_h[(size_t)NN * FHID];    // hs1 = (x@W1)*dis
__device__ float g_agg[(size_t)NN * FHID];  // h   = relu(dis*(sum+self)+b1)
__device__ float g_h2[(size_t)NN * FOUT];   // hs2 = (h@W2)*dis
__device__ int   g_deg[NN];                 // in-degree histogram
__device__ float g_dis[NN];                 // (deg+1)^-1/2
__device__ int   g_starts[NN + 1];          // CSR row starts
__device__ int   g_cursor[NN];              // atomic fill cursors
__device__ int   g_csr_row[EE];             // source node per CSR slot
__device__ int   g_blockoff[64];            // scan block offsets

// ---------------------------------------------------------------------------
// PTX helpers
// ---------------------------------------------------------------------------
__device__ __forceinline__ uint32_t smem_u32(const void* p) {
    return (uint32_t)__cvta_generic_to_shared(p);
}

__device__ __forceinline__ void ldmat_x4(uint32_t& r0, uint32_t& r1, uint32_t& r2, uint32_t& r3,
                                         uint32_t addr) {
    asm volatile("ldmatrix.sync.aligned.m8n8.x4.shared.b16 {%0,%1,%2,%3}, [%4];"
                 : "=r"(r0), "=r"(r1), "=r"(r2), "=r"(r3) : "r"(addr));
}
__device__ __forceinline__ void ldmat_x4_t(uint32_t& r0, uint32_t& r1, uint32_t& r2, uint32_t& r3,
                                           uint32_t addr) {
    asm volatile("ldmatrix.sync.aligned.m8n8.x4.trans.shared.b16 {%0,%1,%2,%3}, [%4];"
                 : "=r"(r0), "=r"(r1), "=r"(r2), "=r"(r3) : "r"(addr));
}

__device__ __forceinline__ void mma_bf16(float* d, const uint32_t* a, uint32_t b0, uint32_t b1) {
    asm volatile(
        "mma.sync.aligned.m16n8k16.row.col.f32.bf16.bf16.f32 "
        "{%0,%1,%2,%3}, {%4,%5,%6,%7}, {%8,%9}, {%0,%1,%2,%3};"
        : "+f"(d[0]), "+f"(d[1]), "+f"(d[2]), "+f"(d[3])
        : "r"(a[0]), "r"(a[1]), "r"(a[2]), "r"(a[3]), "r"(b0), "r"(b1));
}

// pack two fp32 into bf16x2 (hi) and residual bf16x2 (lo)
__device__ __forceinline__ void split2(float v0, float v1, uint32_t& hi, uint32_t& lo) {
    __nv_bfloat16 h0 = __float2bfloat16_rn(v0);
    __nv_bfloat16 h1 = __float2bfloat16_rn(v1);
    __nv_bfloat16 l0 = __float2bfloat16_rn(v0 - __bfloat162float(h0));
    __nv_bfloat16 l1 = __float2bfloat16_rn(v1 - __bfloat162float(h1));
    __nv_bfloat162 ph = {h0, h1}, pl = {l0, l1};
    hi = *(uint32_t*)&ph;
    lo = *(uint32_t*)&pl;
}

// ---------------------------------------------------------------------------
// Zero int buffer
// ---------------------------------------------------------------------------
__global__ void zero_int_kernel(int* __restrict__ p, int n) {
    int i = blockIdx.x * blockDim.x + threadIdx.x;
    if (i < n) p[i] = 0;
}

// ---------------------------------------------------------------------------
// Degree histogram
// ---------------------------------------------------------------------------
__global__ void count_deg_kernel(const int* __restrict__ col, int* __restrict__ deg, int e) {
    int i = blockIdx.x * blockDim.x + threadIdx.x;
    if (i < e) atomicAdd(&deg[col[i]], 1);
}

// ---------------------------------------------------------------------------
// scan1: per-block (1024 elems) totals; also computes dis = rsqrt(deg+1)
// ---------------------------------------------------------------------------
__global__ void __launch_bounds__(256)
scan1_kernel(const int* __restrict__ deg, int* __restrict__ blocksum,
             float* __restrict__ dis, int n) {
    __shared__ int wsum[8];
    int t = threadIdx.x, b = blockIdx.x;
    int base = b * 1024 + t * 4;
    int s = 0;
#pragma unroll
    for (int j = 0; j < 4; j++) {
        int idx = base + j;
        int d = (idx < n) ? deg[idx] : 0;
        s += d;
        if (idx < n) dis[idx] = rsqrtf((float)d + 1.0f);
    }
#pragma unroll
    for (int o = 16; o > 0; o >>= 1) s += __shfl_down_sync(0xffffffffu, s, o);
    if ((t & 31) == 0) wsum[t >> 5] = s;
    __syncthreads();
    if (t == 0) {
        int tot = 0;
#pragma unroll
        for (int w = 0; w < 8; w++) tot += wsum[w];
        blocksum[b] = tot;
    }
}

// scan2: serial exclusive scan of block sums
__global__ void scan2_kernel(const int* __restrict__ blocksum, int* __restrict__ blockoff,
                             int* __restrict__ starts, int nblk, int n) {
    if (threadIdx.x == 0 && blockIdx.x == 0) {
        int run = 0;
        for (int i = 0; i < nblk; i++) { blockoff[i] = run; run += blocksum[i]; }
        starts[n] = run;
    }
}

// scan3: per-block exclusive scan with global offset -> starts + cursor
__global__ void __launch_bounds__(256)
scan3_kernel(const int* __restrict__ deg, const int* __restrict__ blockoff,
             int* __restrict__ starts, int* __restrict__ cursor, int n) {
    __shared__ int wtot[8];
    int t = threadIdx.x, b = blockIdx.x;
    int lane = t & 31, wid = t >> 5;
    int base = b * 1024 + t * 4;
    int v[4];
#pragma unroll
    for (int j = 0; j < 4; j++) {
        int idx = base + j;
        v[j] = (idx < n) ? deg[idx] : 0;
    }
    int tsum = v[0] + v[1] + v[2] + v[3];
    int incl = tsum;
#pragma unroll
    for (int o = 1; o < 32; o <<= 1) {
        int u = __shfl_up_sync(0xffffffffu, incl, o);
        if (lane >= o) incl += u;
    }
    if (lane == 31) wtot[wid] = incl;
    __syncthreads();
    int woff = 0;
#pragma unroll
    for (int w = 0; w < 8; w++) woff += (w < wid) ? wtot[w] : 0;
    int excl = blockoff[b] + woff + incl - tsum;
#pragma unroll
    for (int j = 0; j < 4; j++) {
        int idx = base + j;
        if (idx < n) { starts[idx] = excl; cursor[idx] = excl; }
        excl += v[j];
    }
}

// CSR fill
__global__ void fill_kernel(const int* __restrict__ row, const int* __restrict__ col,
                            int* __restrict__ cursor, int* __restrict__ csr_row, int e) {
    int i = blockIdx.x * blockDim.x + threadIdx.x;
    if (i < e) {
        int slot = atomicAdd(&cursor[col[i]], 1);
        csr_row[slot] = row[i];
    }
}

// ---------------------------------------------------------------------------
// Tensor-core GEMM via split-bf16 (3xBF16 ~ fp32 precision):
//   out[N, F] = (x[N, 128] @ W[128, F]) * dis[row]
//
// Block: 256 threads (8 warps), BM=128 rows (warp w -> rows w*16..w*16+15),
// each warp covers the full F columns. KT=64 (two k-tiles over K=128).
// A and W are converted fp32 -> (hi, lo) bf16 into padded smem:
//   A stride 72 bf16 (144 B), W stride F+8 bf16 -> conflict-free ldmatrix.
// Per k16-step and per n16 pair: 3 MMAs with (Ahi,Bhi),(Ahi,Blo),(Alo,Bhi).
// ---------------------------------------------------------------------------
template <int F>
__global__ void __launch_bounds__(256)
gemm_tc_kernel(const float* __restrict__ x, const float* __restrict__ W,
               float* __restrict__ out, const float* __restrict__ dis, int nrows) {
    constexpr int BM   = 128;
    constexpr int KT   = 64;
    constexpr int NT   = F / 8;          // 8-wide n tiles per warp
    constexpr int ASTR = KT + 8;         // 72 bf16 = 144 B
    constexpr int WSTR = F + 8;          // 136 or 72 bf16

    extern __shared__ __nv_bfloat16 smem[];
    __nv_bfloat16* Ahi = smem;                          // [BM][ASTR]
    __nv_bfloat16* Alo = Ahi + BM * ASTR;
    __nv_bfloat16* Whi = Alo + BM * ASTR;               // [KT][WSTR]
    __nv_bfloat16* Wlo = Whi + KT * WSTR;

    const int tid  = threadIdx.x;
    const int lane = tid & 31;
    const int wr   = tid >> 5;           // warp row (0..7)
    const int row0 = blockIdx.x * BM;

    float acc[NT][4];
#pragma unroll
    for (int nt = 0; nt < NT; nt++)
#pragma unroll
        for (int j = 0; j < 4; j++) acc[nt][j] = 0.f;

    // ldmatrix lane addressing (constant across k-steps except offsets)
    const int mat  = lane >> 3;          // 0..3
    const int mrow = lane & 7;

    for (int kt = 0; kt < FIN; kt += KT) {
        // ---- load & convert A tile: BM x KT fp32 -> hi/lo bf16 ----
        {
            constexpr int NV = (BM * KT) / 4;    // float4 count = 2048
#pragma unroll
            for (int p = tid; p < NV; p += 256) {
                int r  = p / (KT / 4);
                int kq = (p % (KT / 4)) * 4;
                float4 v;
                int grow = row0 + r;
                if (grow < nrows)
                    v = *(const float4*)(x + (size_t)grow * FIN + kt + kq);
                else
                    v = make_float4(0.f, 0.f, 0.f, 0.f);
                uint32_t h01, l01, h23, l23;
                split2(v.x, v.y, h01, l01);
                split2(v.z, v.w, h23, l23);
                *(uint32_t*)(Ahi + r * ASTR + kq)     = h01;
                *(uint32_t*)(Ahi + r * ASTR + kq + 2) = h23;
                *(uint32_t*)(Alo + r * ASTR + kq)     = l01;
                *(uint32_t*)(Alo + r * ASTR + kq + 2) = l23;
            }
        }
        // ---- load & convert W tile: KT x F fp32 -> hi/lo bf16 ----
        {
            constexpr int NV = (KT * F) / 4;
#pragma unroll
            for (int p = tid; p < NV; p += 256) {
                int k = p / (F / 4);
                int c = (p % (F / 4)) * 4;
                float4 v = *(const float4*)(W + (size_t)(kt + k) * F + c);
                uint32_t h01, l01, h23, l23;
                split2(v.x, v.y, h01, l01);
                split2(v.z, v.w, h23, l23);
                *(uint32_t*)(Whi + k * WSTR + c)     = h01;
                *(uint32_t*)(Whi + k * WSTR + c + 2) = h23;
                *(uint32_t*)(Wlo + k * WSTR + c)     = l01;
                *(uint32_t*)(Wlo + k * WSTR + c + 2) = l23;
            }
        }
        __syncthreads();

        // ---- compute: 4 k16-steps ----
#pragma unroll
        for (int ks = 0; ks < KT / 16; ks++) {
            // A fragments (hi & lo)
            uint32_t ah[4], al[4];
            {
                int arow = wr * 16 + (mat & 1) * 8 + mrow;
                int acol = ks * 16 + (mat >> 1) * 8;
                uint32_t a_hi = smem_u32(Ahi + arow * ASTR + acol);
                uint32_t a_lo = smem_u32(Alo + arow * ASTR + acol);
                ldmat_x4(ah[0], ah[1], ah[2], ah[3], a_hi);
                ldmat_x4(al[0], al[1], al[2], al[3], a_lo);
            }
#pragma unroll
            for (int nt2 = 0; nt2 < NT / 2; nt2++) {
                int krow = ks * 16 + (mat & 1) * 8 + mrow;
                int ncol = nt2 * 16 + (mat >> 1) * 8;
                uint32_t w_hi = smem_u32(Whi + krow * WSTR + ncol);
                uint32_t w_lo = smem_u32(Wlo + krow * WSTR + ncol);
                uint32_t bh[4], bl[4];
                ldmat_x4_t(bh[0], bh[1], bh[2], bh[3], w_hi);
                ldmat_x4_t(bl[0], bl[1], bl[2], bl[3], w_lo);
                // n-tile 2*nt2
                mma_bf16(acc[2 * nt2], ah, bh[0], bh[1]);
                mma_bf16(acc[2 * nt2], ah, bl[0], bl[1]);
                mma_bf16(acc[2 * nt2], al, bh[0], bh[1]);
                // n-tile 2*nt2+1
                mma_bf16(acc[2 * nt2 + 1], ah, bh[2], bh[3]);
                mma_bf16(acc[2 * nt2 + 1], ah, bl[2], bl[3]);
                mma_bf16(acc[2 * nt2 + 1], al, bh[2], bh[3]);
            }
        }
        __syncthreads();
    }

    // ---- epilogue: scale by dis[row], write f32 ----
    {
        int r0 = row0 + wr * 16 + (lane >> 2);
        int r1 = r0 + 8;
        float s0 = (r0 < nrows) ? __ldg(dis + r0) : 0.f;
        float s1 = (r1 < nrows) ? __ldg(dis + r1) : 0.f;
        int cbase = (lane & 3) * 2;
#pragma unroll
        for (int nt = 0; nt < NT; nt++) {
            int c = nt * 8 + cbase;
            if (r0 < nrows) {
                float2 v0 = make_float2(acc[nt][0] * s0, acc[nt][1] * s0);
                *(float2*)(out + (size_t)r0 * F + c) = v0;
            }
            if (r1 < nrows) {
                float2 v1 = make_float2(acc[nt][2] * s1, acc[nt][3] * s1);
                *(float2*)(out + (size_t)r1 * F + c) = v1;
            }
        }
    }
}

// ---------------------------------------------------------------------------
// CSR segment-sum aggregate (fused self-loop + dis scale + bias [+ relu])
// ---------------------------------------------------------------------------
template <int F, bool RELU>
__global__ void __launch_bounds__(256)
aggregate_kernel(const float* __restrict__ hs,
                 const int* __restrict__ csr_row, const int* __restrict__ starts,
                 const float* __restrict__ dis, const float* __restrict__ bias,
                 float* __restrict__ out, int n) {
    constexpr int LPN = F / 4;
    const int gtid = blockIdx.x * blockDim.x + threadIdx.x;
    const int node = gtid / LPN;
    const int sub  = gtid % LPN;
    if (node >= n) return;

    const int beg = __ldg(starts + node);
    const int end = __ldg(starts + node + 1);

    float4 a0 = *(const float4*)(hs + (size_t)node * F + sub * 4);  // self loop
    float4 a1 = make_float4(0.f, 0.f, 0.f, 0.f);

    int e = beg;
    for (; e + 1 < end; e += 2) {
        int r0 = __ldg(csr_row + e);
        int r1 = __ldg(csr_row + e + 1);
        float4 v0 = *(const float4*)(hs + (size_t)r0 * F + sub * 4);
        float4 v1 = *(const float4*)(hs + (size_t)r1 * F + sub * 4);
        a0.x += v0.x; a0.y += v0.y; a0.z += v0.z; a0.w += v0.w;
        a1.x += v1.x; a1.y += v1.y; a1.z += v1.z; a1.w += v1.w;
    }
    if (e < end) {
        int r0 = __ldg(csr_row + e);
        float4 v0 = *(const float4*)(hs + (size_t)r0 * F + sub * 4);
        a0.x += v0.x; a0.y += v0.y; a0.z += v0.z; a0.w += v0.w;
    }

    const float d = __ldg(dis + node);
    float4 bv = *(const float4*)(bias + sub * 4);
    float4 o;
    o.x = (a0.x + a1.x) * d + bv.x;
    o.y = (a0.y + a1.y) * d + bv.y;
    o.z = (a0.z + a1.z) * d + bv.z;
    o.w = (a0.w + a1.w) * d + bv.w;
    if (RELU) {
        o.x = fmaxf(o.x, 0.f); o.y = fmaxf(o.y, 0.f);
        o.z = fmaxf(o.z, 0.f); o.w = fmaxf(o.w, 0.f);
    }
    *(float4*)(out + (size_t)node * F + sub * 4) = o;
}

// ---------------------------------------------------------------------------
// Launch
// ---------------------------------------------------------------------------
extern "C" void kernel_launch(void* const* d_in, const int* in_sizes, int n_in,
                              void* d_out, int out_size) {
    const float* x  = (const float*)d_in[0];
    const int*   ei = (const int*)d_in[1];
    const float* W1 = (const float*)d_in[2];
    const float* b1 = (const float*)d_in[3];
    const float* W2 = (const float*)d_in[4];
    const float* b2 = (const float*)d_in[5];
    float* out = (float*)d_out;

    const int* row = ei;
    const int* col = ei + EE;

    // smem sizes for the tensor GEMMs
    constexpr int SMEM1 = (128 * 72 * 2 + 64 * 136 * 2) * 2;  // bytes: A(hi+lo)+W(hi+lo), F=128
    constexpr int SMEM2 = (128 * 72 * 2 + 64 * 72 * 2) * 2;   // F=64

    static float *p_h = nullptr, *p_agg = nullptr, *p_h2 = nullptr, *p_dis = nullptr;
    static int *p_deg = nullptr, *p_starts = nullptr, *p_cursor = nullptr,
               *p_csr = nullptr, *p_boff = nullptr;
    if (!p_h) {
        cudaGetSymbolAddress((void**)&p_h,      g_h);
        cudaGetSymbolAddress((void**)&p_agg,    g_agg);
        cudaGetSymbolAddress((void**)&p_h2,     g_h2);
        cudaGetSymbolAddress((void**)&p_dis,    g_dis);
        cudaGetSymbolAddress((void**)&p_deg,    g_deg);
        cudaGetSymbolAddress((void**)&p_starts, g_starts);
        cudaGetSymbolAddress((void**)&p_cursor, g_cursor);
        cudaGetSymbolAddress((void**)&p_csr,    g_csr_row);
        cudaGetSymbolAddress((void**)&p_boff,   g_blockoff);
        cudaFuncSetAttribute(gemm_tc_kernel<128>,
                             cudaFuncAttributeMaxDynamicSharedMemorySize, SMEM1);
        cudaFuncSetAttribute(gemm_tc_kernel<64>,
                             cudaFuncAttributeMaxDynamicSharedMemorySize, SMEM2);
    }

    const int NBLK = (NN + 1023) / 1024;   // 49

    // ---- degree histogram + CSR build ----
    zero_int_kernel<<<(NN + 255) / 256, 256>>>(p_deg, NN);
    count_deg_kernel<<<(EE + 255) / 256, 256>>>(col, p_deg, EE);
    scan1_kernel<<<NBLK, 256>>>(p_deg, p_boff, p_dis, NN);
    scan2_kernel<<<1, 32>>>(p_boff, p_boff, p_starts, NBLK, NN);
    scan3_kernel<<<NBLK, 256>>>(p_deg, p_boff, p_starts, p_cursor, NN);
    fill_kernel<<<(EE + 255) / 256, 256>>>(row, col, p_cursor, p_csr, EE);

    const int GBLK = (NN + 127) / 128;     // 391

    // ---- layer 1: tensor GEMM (hs1 = (x@W1)*dis) ----
    gemm_tc_kernel<128><<<GBLK, 256, SMEM1>>>(x, W1, p_h, p_dis, NN);

    // ---- layer 1 aggregate -> g_agg = h ----
    {
        long long threads = (long long)NN * 32;
        aggregate_kernel<128, true><<<(int)((threads + 255) / 256), 256>>>(
            p_h, p_csr, p_starts, p_dis, b1, p_agg, NN);
    }

    // ---- layer 2: tensor GEMM (hs2 = (h@W2)*dis) ----
    gemm_tc_kernel<64><<<GBLK, 256, SMEM2>>>(p_agg, W2, p_h2, p_dis, NN);

    // ---- layer 2 aggregate -> d_out ----
    {
        long long threads = (long long)NN * 16;
        aggregate_kernel<64, false><<<(int)((threads + 255) / 256), 256>>>(
            p_h2, p_csr, p_starts, p_dis, b2, out, NN);
    }
}